// round 1
// baseline (speedup 1.0000x reference)
#include <cuda_runtime.h>

// ---------------- problem constants ----------------
#define B_      8
#define IN_C    32
#define OUT_C   64
#define H_      64
#define W_      64
#define KS      3
#define QDIM    36      // grid_dim_x
#define PDIM    8       // grid_dim_y
#define KB      8       // miniblock
#define NPIX    (B_*H_*W_)          // 32768

#define HP      66
#define CHW     (HP*HP)             // 4356
#define PAD_TOTAL (B_*IN_C*CHW)     // 1,115,136

// MRR constants (A=0.987, R=0.99)
#define MRR_A   0.987
#define MRR_R   0.99

__device__ float g_xpad[PAD_TOTAL];

// ---------------- kernel 1: zero-padded x^2 ----------------
__global__ void prepad_kernel(const float* __restrict__ x) {
    int idx = blockIdx.x * blockDim.x + threadIdx.x;
    if (idx >= PAD_TOTAL) return;
    int wp = idx % HP;
    int t  = idx / HP;
    int hp = t % HP;
    int bc = t / HP;               // b*IN_C + c
    float v = 0.0f;
    if (hp >= 1 && hp <= H_ && wp >= 1 && wp <= W_) {
        float xv = x[(bc * H_ + (hp - 1)) * W_ + (wp - 1)];
        v = xv * xv;
    }
    g_xpad[idx] = v;
}

// ---------------- kernel 2: main compute ----------------
// thread = (pixel n, p-half). acc over 4 p x 8 t.
__global__ __launch_bounds__(64) void morr_kernel(const float* __restrict__ wgt,
                                                  const float* __restrict__ mos,
                                                  float* __restrict__ out) {
    __shared__ float wsh[QDIM * PDIM * KB];   // [q][p][s], |w|
    __shared__ int   poff[QDIM * KB];         // unfold offsets into padded buf
    __shared__ float scl[QDIM];               // -D * scale[q]

    const int tid = threadIdx.x;

    // stage |weights| rearranged to [q][p][s]
    for (int d = tid; d < QDIM * PDIM * KB; d += 64) {
        int q = d >> 6;            // d / 64
        int p = (d >> 3) & 7;
        int s = d & 7;
        wsh[d] = fabsf(wgt[p * (QDIM * KB) + q * KB + s]);
    }
    // unfold offset table: idx = q*8+s -> (c, kh, kw), c slowest
    for (int i = tid; i < QDIM * KB; i += 64) {
        int c = i / 9, r = i % 9;
        poff[i] = c * CHW + (r / 3) * HP + (r % 3);
    }
    // differential-rail scale, folded with -D
    if (tid < QDIM) {
        const float D = (float)((1.0 - MRR_A * MRR_A) * (1.0 - MRR_R * MRR_R));
        float sv = (tid < QDIM / 2) ? mos[tid] : -mos[tid - QDIM / 2];
        scl[tid] = -D * sv;
    }
    __syncthreads();

    const int phalf = blockIdx.x & 1;                 // p in [4*phalf, 4*phalf+4)
    const int n = ((int)blockIdx.x >> 1) * 64 + tid;  // pixel index
    const int b = n >> 12;
    const int h = (n >> 6) & 63;
    const int w = n & 63;

    const float* __restrict__ xb = g_xpad + b * (IN_C * CHW) + h * HP + w;

    float acc[32];
#pragma unroll
    for (int i = 0; i < 32; ++i) acc[i] = 0.0f;

    const float C2   = (float)(1.0 + (MRR_A * MRR_R) * (MRR_A * MRR_R));
    const float N2AR = (float)(-2.0 * MRR_A * MRR_R);

#pragma unroll 2
    for (int q = 0; q < QDIM; ++q) {
        float xs[8];
#pragma unroll
        for (int s = 0; s < 8; ++s) xs[s] = xb[poff[q * 8 + s]];
        const float sq = scl[q];
        const float* wq = &wsh[q * 64 + phalf * 32];

#pragma unroll
        for (int pp = 0; pp < 4; ++pp) {
            float4 wa = *(const float4*)(wq + pp * 8);
            float4 wb = *(const float4*)(wq + pp * 8 + 4);
            float wr[8];
            wr[0] = wa.x; wr[1] = wa.y; wr[2] = wa.z; wr[3] = wa.w;
            wr[4] = wb.x; wr[5] = wb.y; wr[6] = wb.z; wr[7] = wb.w;
#pragma unroll
            for (int t = 0; t < 8; ++t) {
                // circular convolution: phase[t] = sum_s xs[s] * w[(t-s) mod 8]
                float ph = xs[0] * wr[t];
#pragma unroll
                for (int s = 1; s < 8; ++s) ph = fmaf(xs[s], wr[(t - s) & 7], ph);
                // tr = 1 - D / (C2 - 2AR*cos(ph)); sum_q scale[q] == 0 kills the 1-term
                float cc = __cosf(ph);
                float e  = fmaf(cc, N2AR, C2);
                float r;
                asm("rcp.approx.f32 %0, %1;" : "=f"(r) : "f"(e));
                acc[pp * 8 + t] = fmaf(sq, r, acc[pp * 8 + t]);
            }
        }
    }

    // out[b][ch][h][w], ch = phalf*32 + pp*8 + t
    float* __restrict__ ob = out + (b * OUT_C + phalf * 32) * (H_ * W_) + h * W_ + w;
#pragma unroll
    for (int i = 0; i < 32; ++i) ob[i * (H_ * W_)] = acc[i];
}

// ---------------- launch ----------------
extern "C" void kernel_launch(void* const* d_in, const int* in_sizes, int n_in,
                              void* d_out, int out_size) {
    const float* x   = (const float*)d_in[0];
    const float* wgt = (const float*)d_in[1];
    const float* mos = (const float*)d_in[2];
    float* out = (float*)d_out;

    prepad_kernel<<<(PAD_TOTAL + 255) / 256, 256>>>(x);
    morr_kernel<<<(NPIX / 64) * 2, 64>>>(wgt, mos, out);
}

// round 2
// speedup vs baseline: 1.1940x; 1.1940x over previous
#include <cuda_runtime.h>

// ---------------- problem constants ----------------
#define B_      8
#define IN_C    32
#define OUT_C   64
#define H_      64
#define W_      64
#define QDIM    36
#define PDIM    8
#define KB      8
#define NPIX    (B_*H_*W_)          // 32768
#define NQP     (QDIM/2)            // 18 q-pairs

#define HP      66
#define CHW     (HP*HP)             // 4356
#define PAD_TOTAL (B_*IN_C*CHW)

#define MRR_A   0.987
#define MRR_R   0.99

typedef unsigned long long u64;

__device__ float g_xpad[PAD_TOTAL];

// ---------------- kernel 1: zero-padded x^2 ----------------
__global__ void prepad_kernel(const float* __restrict__ x) {
    int idx = blockIdx.x * blockDim.x + threadIdx.x;
    if (idx >= PAD_TOTAL) return;
    int wp = idx % HP;
    int t  = idx / HP;
    int hp = t % HP;
    int bc = t / HP;
    float v = 0.0f;
    if (hp >= 1 && hp <= H_ && wp >= 1 && wp <= W_) {
        float xv = x[(bc * H_ + (hp - 1)) * W_ + (wp - 1)];
        v = xv * xv;
    }
    g_xpad[idx] = v;
}

// ---------------- packed f32x2 helpers ----------------
__device__ __forceinline__ u64 pack2(float a, float b) {
    u64 r;
    asm("mov.b64 %0, {%1, %2};" : "=l"(r) : "f"(a), "f"(b));
    return r;
}
__device__ __forceinline__ void unpack2(u64 v, float& a, float& b) {
    asm("mov.b64 {%0, %1}, %2;" : "=f"(a), "=f"(b) : "l"(v));
}
__device__ __forceinline__ u64 mul2(u64 a, u64 b) {
    u64 r;
    asm("mul.rn.f32x2 %0, %1, %2;" : "=l"(r) : "l"(a), "l"(b));
    return r;
}
__device__ __forceinline__ u64 fma2(u64 a, u64 b, u64 c) {
    u64 r;
    asm("fma.rn.f32x2 %0, %1, %2, %3;" : "=l"(r) : "l"(a), "l"(b), "l"(c));
    return r;
}

// ---------------- kernel 2: main compute ----------------
// block = 128 threads: warp w -> psplit w (p in {2w, 2w+1}), lanes -> 32 consecutive pixels.
__global__ __launch_bounds__(128, 7) void morr_kernel(const float* __restrict__ wgt,
                                                      const float* __restrict__ mos,
                                                      float* __restrict__ out) {
    // weights prepacked across the q-pair: wpk[qp][p][i] = { |w[2qp,p,i]|, |w[2qp+1,p,i]| }
    __shared__ float2 wpk[NQP * PDIM * KB];   // 9216 B
    __shared__ int    poff[QDIM * KB];        // unfold offsets
    __shared__ float  scl[QDIM];              // -D * rail-scale[q]

    const int tid = threadIdx.x;

    for (int d = tid; d < NQP * PDIM * KB; d += 128) {
        int qp = d >> 6;
        int p  = (d >> 3) & 7;
        int i  = d & 7;
        float w0 = fabsf(wgt[p * (QDIM * KB) + (2 * qp)     * KB + i]);
        float w1 = fabsf(wgt[p * (QDIM * KB) + (2 * qp + 1) * KB + i]);
        wpk[d] = make_float2(w0, w1);
    }
    for (int i = tid; i < QDIM * KB; i += 128) {
        int c = i / 9, r = i % 9;
        poff[i] = c * CHW + (r / 3) * HP + (r % 3);
    }
    if (tid < QDIM) {
        const float D = (float)((1.0 - MRR_A * MRR_A) * (1.0 - MRR_R * MRR_R));
        float sv = (tid < QDIM / 2) ? mos[tid] : -mos[tid - QDIM / 2];
        scl[tid] = -D * sv;
    }
    __syncthreads();

    const int psplit = tid >> 5;                  // 0..3
    const int lane   = tid & 31;
    const int n = blockIdx.x * 32 + lane;         // pixel
    const int b = n >> 12;
    const int h = (n >> 6) & 63;
    const int w = n & 63;

    const float* __restrict__ xb = g_xpad + b * (IN_C * CHW) + h * HP + w;

    float acc[2][8];
#pragma unroll
    for (int pl = 0; pl < 2; ++pl)
#pragma unroll
        for (int t = 0; t < 8; ++t) acc[pl][t] = 0.0f;

    const float C2   = (float)(1.0 + (MRR_A * MRR_R) * (MRR_A * MRR_R));
    const float N2AR = (float)(-2.0 * MRR_A * MRR_R);

    for (int qp = 0; qp < NQP; ++qp) {
        const float a0 = scl[2 * qp];
        const float a1 = scl[2 * qp + 1];

        // gather both q's inputs, pack across q
        u64 xsp[8];
#pragma unroll
        for (int s = 0; s < 8; ++s) {
            float x0 = xb[poff[qp * 16 + s]];
            float x1 = xb[poff[qp * 16 + 8 + s]];
            xsp[s] = pack2(x0, x1);
        }

#pragma unroll
        for (int pl = 0; pl < 2; ++pl) {
            const int p = psplit * 2 + pl;
            const u64* __restrict__ wq =
                reinterpret_cast<const u64*>(wpk + (qp * PDIM + p) * KB);
            u64 wr[8];
#pragma unroll
            for (int i = 0; i < 8; ++i) wr[i] = wq[i];   // LDS.64, already packed

#pragma unroll
            for (int t = 0; t < 8; ++t) {
                // packed circular conv: {phase_q0[t], phase_q1[t]}
                u64 ph = mul2(xsp[0], wr[t]);
#pragma unroll
                for (int s = 1; s < 8; ++s) ph = fma2(xsp[s], wr[(t - s) & 7], ph);

                float ph0, ph1;
                unpack2(ph, ph0, ph1);
                float c0 = __cosf(ph0);
                float c1 = __cosf(ph1);
                float e0 = fmaf(c0, N2AR, C2);
                float e1 = fmaf(c1, N2AR, C2);
                // a0/e0 + a1/e1 = (a0*e1 + a1*e0) / (e0*e1): one RCP per q-pair
                float num = fmaf(a1, e0, a0 * e1);
                float den = e0 * e1;
                float r;
                asm("rcp.approx.f32 %0, %1;" : "=f"(r) : "f"(den));
                acc[pl][t] = fmaf(num, r, acc[pl][t]);
            }
        }
    }

    // out[b][ch][h][w], ch = (psplit*2 + pl)*8 + t
    float* __restrict__ ob = out + (b * OUT_C + psplit * 16) * (H_ * W_) + h * W_ + w;
#pragma unroll
    for (int pl = 0; pl < 2; ++pl)
#pragma unroll
        for (int t = 0; t < 8; ++t)
            ob[(pl * 8 + t) * (H_ * W_)] = acc[pl][t];
}

// ---------------- launch ----------------
extern "C" void kernel_launch(void* const* d_in, const int* in_sizes, int n_in,
                              void* d_out, int out_size) {
    const float* x   = (const float*)d_in[0];
    const float* wgt = (const float*)d_in[1];
    const float* mos = (const float*)d_in[2];
    float* out = (float*)d_out;

    prepad_kernel<<<(PAD_TOTAL + 255) / 256, 256>>>(x);
    morr_kernel<<<NPIX / 32, 128>>>(wgt, mos, out);
}